// round 10
// baseline (speedup 1.0000x reference)
#include <cuda_runtime.h>
#include <math.h>

// SVDHead: weighted Kabsch over B=256 batches, N=65536 points.
// Split design (fusion regressed twice — R7/R9):
//   Kernel 1: streaming reduction, CHUNKS=4 chunks/batch (fewer waves).
//   Kernel 2: ONE block, 256 threads, one batch per thread — all 256 fp32
//             solves run SIMD-parallel (vs 6.9us of 1-thread-per-block).

#define B_DIM 256
#define N_DIM 65536
#define CHUNKS 4
#define TPB 256
#define NV 22   // 3 sum_s, 3 sum_t, 1 sum_w, 3 sum_ws, 3 sum_wt, 9 sum_w_s_t

__device__ float g_scratch[B_DIM * CHUNKS * NV];

// ---------------------------------------------------------------------------
// Kernel 1: per-(batch,chunk) partial reduction. grid = B*CHUNKS = 1024,
// 16 float4 iterations per thread per stream.
// ---------------------------------------------------------------------------
__global__ __launch_bounds__(TPB) void svd_reduce_kernel(
    const float* __restrict__ src,
    const float* __restrict__ tgt,
    const float* __restrict__ wgt)
{
    const int bc = blockIdx.x;
    const int b = bc >> 2;          // CHUNKS = 4
    const int c = bc & 3;

    const float4* s0 = (const float4*)(src + (size_t)b * 3 * N_DIM);
    const float4* s1 = s0 + (N_DIM / 4);
    const float4* s2 = s0 + 2 * (N_DIM / 4);
    const float4* t0 = (const float4*)(tgt + (size_t)b * 3 * N_DIM);
    const float4* t1 = t0 + (N_DIM / 4);
    const float4* t2 = t0 + 2 * (N_DIM / 4);
    const float4* w4 = (const float4*)(wgt + (size_t)b * N_DIM);

    // N/4 = 16384 float4 per row; per chunk: 4096 float4; per thread: 16.
    const int base = c * (N_DIM / 4 / CHUNKS) + threadIdx.x;

    float a[NV];
#pragma unroll
    for (int k = 0; k < NV; k++) a[k] = 0.0f;

#define ACC_ONE(sx, sy, sz, tx, ty, tz, ww)                               \
    {                                                                     \
        a[0] += (sx); a[1] += (sy); a[2] += (sz);                         \
        a[3] += (tx); a[4] += (ty); a[5] += (tz);                         \
        a[6] += (ww);                                                     \
        float ws0 = (ww) * (sx), ws1 = (ww) * (sy), ws2 = (ww) * (sz);    \
        a[7] += ws0; a[8] += ws1; a[9] += ws2;                            \
        a[10] += (ww) * (tx); a[11] += (ww) * (ty); a[12] += (ww) * (tz); \
        a[13] += ws0 * (tx); a[14] += ws0 * (ty); a[15] += ws0 * (tz);    \
        a[16] += ws1 * (tx); a[17] += ws1 * (ty); a[18] += ws1 * (tz);    \
        a[19] += ws2 * (tx); a[20] += ws2 * (ty); a[21] += ws2 * (tz);    \
    }

#pragma unroll
    for (int k = 0; k < 16; k++) {
        const int idx = base + k * TPB;
        float4 vs0 = s0[idx], vs1 = s1[idx], vs2 = s2[idx];
        float4 vt0 = t0[idx], vt1 = t1[idx], vt2 = t2[idx];
        float4 vw  = w4[idx];
        ACC_ONE(vs0.x, vs1.x, vs2.x, vt0.x, vt1.x, vt2.x, vw.x);
        ACC_ONE(vs0.y, vs1.y, vs2.y, vt0.y, vt1.y, vt2.y, vw.y);
        ACC_ONE(vs0.z, vs1.z, vs2.z, vt0.z, vt1.z, vt2.z, vw.z);
        ACC_ONE(vs0.w, vs1.w, vs2.w, vt0.w, vt1.w, vt2.w, vw.w);
    }
#undef ACC_ONE

#pragma unroll
    for (int off = 16; off > 0; off >>= 1) {
#pragma unroll
        for (int k = 0; k < NV; k++)
            a[k] += __shfl_down_sync(0xFFFFFFFFu, a[k], off);
    }

    __shared__ float smem[TPB / 32][NV];
    const int warp = threadIdx.x >> 5;
    const int lane = threadIdx.x & 31;
    if (lane == 0) {
#pragma unroll
        for (int k = 0; k < NV; k++) smem[warp][k] = a[k];
    }
    __syncthreads();

    if (threadIdx.x < NV) {
        float s = 0.0f;
#pragma unroll
        for (int wgi = 0; wgi < TPB / 32; wgi++) s += smem[wgi][threadIdx.x];
        g_scratch[(size_t)bc * NV + threadIdx.x] = s;
    }
}

// ---------------------------------------------------------------------------
// Kernel 2: ONE block, 256 threads. Thread b solves batch b (fp32).
// ---------------------------------------------------------------------------
__global__ __launch_bounds__(TPB) void svd_solve_kernel(float* __restrict__ out)
{
    const int b = threadIdx.x;

    // Combine the CHUNKS partials in fixed order (deterministic).
    float sums[NV];
#pragma unroll
    for (int k = 0; k < NV; k++) {
        float s = 0.0f;
#pragma unroll
        for (int c = 0; c < CHUNKS; c++)
            s += g_scratch[((size_t)b * CHUNKS + c) * NV + k];
        sums[k] = s;
    }

    const float invN = 1.0f / (float)N_DIM;
    float ms[3], mt[3], Sws[3], Swt[3], Sw, M[3][3];
#pragma unroll
    for (int i = 0; i < 3; i++) {
        ms[i]  = sums[i] * invN;
        mt[i]  = sums[3 + i] * invN;
        Sws[i] = sums[7 + i];
        Swt[i] = sums[10 + i];
    }
    Sw = sums[6];
#pragma unroll
    for (int i = 0; i < 3; i++)
#pragma unroll
        for (int j = 0; j < 3; j++)
            M[i][j] = sums[13 + i * 3 + j];

    // H_ij = sum w s_i t_j - ms_i*sum(w t_j) - mt_j*sum(w s_i) + ms_i mt_j sum(w)
    float H[3][3];
#pragma unroll
    for (int i = 0; i < 3; i++)
#pragma unroll
        for (int j = 0; j < 3; j++)
            H[i][j] = M[i][j] - ms[i] * Swt[j] - mt[j] * Sws[i] + ms[i] * mt[j] * Sw;

    // S = H^T H (symmetric PSD)
    float S[3][3];
#pragma unroll
    for (int i = 0; i < 3; i++)
#pragma unroll
        for (int j = 0; j < 3; j++) {
            float acc = 0.0f;
#pragma unroll
            for (int k = 0; k < 3; k++) acc += H[k][i] * H[k][j];
            S[i][j] = acc;
        }

    const float trS = S[0][0] + S[1][1] + S[2][2];
    const float tol = 1e-13f * trS * trS + 1e-35f;

    // Cyclic Jacobi eigen-decomposition in fp32: S = V diag(l) V^T.
    float V[3][3] = {{1, 0, 0}, {0, 1, 0}, {0, 0, 1}};
    for (int sweep = 0; sweep < 5; sweep++) {
        float offm = S[0][1] * S[0][1] + S[0][2] * S[0][2] + S[1][2] * S[1][2];
        if (offm < tol) break;
#pragma unroll
        for (int pq = 0; pq < 3; pq++) {
            const int p = (pq == 2) ? 1 : 0;
            const int q = (pq == 0) ? 1 : 2;
            float apq = S[p][q];
            if (fabsf(apq) < 1e-30f) continue;
            float theta = (S[q][q] - S[p][p]) * __fdividef(0.5f, apq);
            float t = copysignf(1.0f, theta) *
                      __fdividef(1.0f, fabsf(theta) + sqrtf(theta * theta + 1.0f));
            float cth = rsqrtf(1.0f + t * t);
            float sth = t * cth;
            float app = S[p][p], aqq = S[q][q];
            S[p][p] = app - t * apq;
            S[q][q] = aqq + t * apq;
            S[p][q] = S[q][p] = 0.0f;
            const int r = 3 - p - q;
            float arp = S[r][p], arq = S[r][q];
            S[r][p] = S[p][r] = cth * arp - sth * arq;
            S[r][q] = S[q][r] = sth * arp + cth * arq;
#pragma unroll
            for (int k = 0; k < 3; k++) {
                float vkp = V[k][p], vkq = V[k][q];
                V[k][p] = cth * vkp - sth * vkq;
                V[k][q] = sth * vkp + cth * vkq;
            }
        }
    }

    // Sort eigenvalues descending; take top-2 eigenvectors.
    float lam[3] = {S[0][0], S[1][1], S[2][2]};
    int i0 = 0, i1 = 1, i2 = 2, tmp;
    if (lam[i0] < lam[i1]) { tmp = i0; i0 = i1; i1 = tmp; }
    if (lam[i0] < lam[i2]) { tmp = i0; i0 = i2; i2 = tmp; }
    if (lam[i1] < lam[i2]) { tmp = i1; i1 = i2; i2 = tmp; }

    float v1[3] = {V[0][i0], V[1][i0], V[2][i0]};
    float v2[3] = {V[0][i1], V[1][i1], V[2][i1]};
    float v3[3] = {v1[1] * v2[2] - v1[2] * v2[1],
                   v1[2] * v2[0] - v1[0] * v2[2],
                   v1[0] * v2[1] - v1[1] * v2[0]};

    // u1 = normalize(H v1); u2 = normalize(GS(H v2, u1)); u3 = u1 x u2.
    float u1[3], u2[3], u3[3];
#pragma unroll
    for (int i = 0; i < 3; i++)
        u1[i] = H[i][0] * v1[0] + H[i][1] * v1[1] + H[i][2] * v1[2];
    float in1 = rsqrtf(u1[0] * u1[0] + u1[1] * u1[1] + u1[2] * u1[2] + 1e-35f);
#pragma unroll
    for (int i = 0; i < 3; i++) u1[i] *= in1;

#pragma unroll
    for (int i = 0; i < 3; i++)
        u2[i] = H[i][0] * v2[0] + H[i][1] * v2[1] + H[i][2] * v2[2];
    float d12 = u2[0] * u1[0] + u2[1] * u1[1] + u2[2] * u1[2];
#pragma unroll
    for (int i = 0; i < 3; i++) u2[i] -= d12 * u1[i];
    float in2 = rsqrtf(u2[0] * u2[0] + u2[1] * u2[1] + u2[2] * u2[2] + 1e-35f);
#pragma unroll
    for (int i = 0; i < 3; i++) u2[i] *= in2;

    u3[0] = u1[1] * u2[2] - u1[2] * u2[1];
    u3[1] = u1[2] * u2[0] - u1[0] * u2[2];
    u3[2] = u1[0] * u2[1] - u1[1] * u2[0];

    // R = v1 u1^T + v2 u2^T + v3 u3^T (proper rotation, det=+1).
    float R[3][3];
#pragma unroll
    for (int i = 0; i < 3; i++)
#pragma unroll
        for (int j = 0; j < 3; j++)
            R[i][j] = v1[i] * u1[j] + v2[i] * u2[j] + v3[i] * u3[j];

    // t = -R @ src_mean + tgt_mean ; t_out = -R^T t ; Rt = R^T
    float tv[3];
#pragma unroll
    for (int i = 0; i < 3; i++)
        tv[i] = -(R[i][0] * ms[0] + R[i][1] * ms[1] + R[i][2] * ms[2]) + mt[i];

    float* outR = out + (size_t)b * 9;
    float* outT = out + (size_t)B_DIM * 9 + (size_t)b * 3;
#pragma unroll
    for (int i = 0; i < 3; i++) {
#pragma unroll
        for (int j = 0; j < 3; j++)
            outR[i * 3 + j] = R[j][i];  // Rt = R^T
        outT[i] = -(R[0][i] * tv[0] + R[1][i] * tv[1] + R[2][i] * tv[2]);
    }
}

extern "C" void kernel_launch(void* const* d_in, const int* in_sizes, int n_in,
                              void* d_out, int out_size)
{
    const float* src = (const float*)d_in[0];
    const float* tgt = (const float*)d_in[1];
    const float* wgt = (const float*)d_in[2];
    float* out = (float*)d_out;

    svd_reduce_kernel<<<B_DIM * CHUNKS, TPB>>>(src, tgt, wgt);
    svd_solve_kernel<<<1, TPB>>>(out);
}

// round 11
// speedup vs baseline: 1.0715x; 1.0715x over previous
#include <cuda_runtime.h>
#include <math.h>

// SVDHead: weighted Kabsch over B=256 batches, N=65536 points.
// Split design (R6 config: fastest measured reduce AND solve layout):
//   Kernel 1: streaming reduction, CHUNKS=8 (71.3us, ~83% HBM).
//   Kernel 2: 256 blocks x 32 threads; closed-form 3x3 eigensolver replaces
//             iterative Jacobi (serial chain ~2000cyc -> ~500cyc).

#define B_DIM 256
#define N_DIM 65536
#define CHUNKS 8
#define TPB 256
#define NV 22   // 3 sum_s, 3 sum_t, 1 sum_w, 3 sum_ws, 3 sum_wt, 9 sum_w_s_t

__device__ float g_scratch[B_DIM * CHUNKS * NV];

// ---------------------------------------------------------------------------
// Kernel 1: per-(batch,chunk) partial reduction (identical to R6 — proven).
// ---------------------------------------------------------------------------
__global__ __launch_bounds__(TPB) void svd_reduce_kernel(
    const float* __restrict__ src,
    const float* __restrict__ tgt,
    const float* __restrict__ wgt)
{
    const int bc = blockIdx.x;
    const int b = bc >> 3;          // CHUNKS = 8
    const int c = bc & 7;

    const float4* s0 = (const float4*)(src + (size_t)b * 3 * N_DIM);
    const float4* s1 = s0 + (N_DIM / 4);
    const float4* s2 = s0 + 2 * (N_DIM / 4);
    const float4* t0 = (const float4*)(tgt + (size_t)b * 3 * N_DIM);
    const float4* t1 = t0 + (N_DIM / 4);
    const float4* t2 = t0 + 2 * (N_DIM / 4);
    const float4* w4 = (const float4*)(wgt + (size_t)b * N_DIM);

    const int base = c * (N_DIM / 4 / CHUNKS) + threadIdx.x;

    float a[NV];
#pragma unroll
    for (int k = 0; k < NV; k++) a[k] = 0.0f;

#define ACC_ONE(sx, sy, sz, tx, ty, tz, ww)                               \
    {                                                                     \
        a[0] += (sx); a[1] += (sy); a[2] += (sz);                         \
        a[3] += (tx); a[4] += (ty); a[5] += (tz);                         \
        a[6] += (ww);                                                     \
        float ws0 = (ww) * (sx), ws1 = (ww) * (sy), ws2 = (ww) * (sz);    \
        a[7] += ws0; a[8] += ws1; a[9] += ws2;                            \
        a[10] += (ww) * (tx); a[11] += (ww) * (ty); a[12] += (ww) * (tz); \
        a[13] += ws0 * (tx); a[14] += ws0 * (ty); a[15] += ws0 * (tz);    \
        a[16] += ws1 * (tx); a[17] += ws1 * (ty); a[18] += ws1 * (tz);    \
        a[19] += ws2 * (tx); a[20] += ws2 * (ty); a[21] += ws2 * (tz);    \
    }

#pragma unroll
    for (int k = 0; k < 8; k++) {
        const int idx = base + k * TPB;
        float4 vs0 = s0[idx], vs1 = s1[idx], vs2 = s2[idx];
        float4 vt0 = t0[idx], vt1 = t1[idx], vt2 = t2[idx];
        float4 vw  = w4[idx];
        ACC_ONE(vs0.x, vs1.x, vs2.x, vt0.x, vt1.x, vt2.x, vw.x);
        ACC_ONE(vs0.y, vs1.y, vs2.y, vt0.y, vt1.y, vt2.y, vw.y);
        ACC_ONE(vs0.z, vs1.z, vs2.z, vt0.z, vt1.z, vt2.z, vw.z);
        ACC_ONE(vs0.w, vs1.w, vs2.w, vt0.w, vt1.w, vt2.w, vw.w);
    }
#undef ACC_ONE

#pragma unroll
    for (int off = 16; off > 0; off >>= 1) {
#pragma unroll
        for (int k = 0; k < NV; k++)
            a[k] += __shfl_down_sync(0xFFFFFFFFu, a[k], off);
    }

    __shared__ float smem[TPB / 32][NV];
    const int warp = threadIdx.x >> 5;
    const int lane = threadIdx.x & 31;
    if (lane == 0) {
#pragma unroll
        for (int k = 0; k < NV; k++) smem[warp][k] = a[k];
    }
    __syncthreads();

    if (threadIdx.x < NV) {
        float s = 0.0f;
#pragma unroll
        for (int wgi = 0; wgi < TPB / 32; wgi++) s += smem[wgi][threadIdx.x];
        g_scratch[(size_t)bc * NV + threadIdx.x] = s;
    }
}

// ---------------------------------------------------------------------------
// Eigenvector of symmetric S for eigenvalue lam, via largest cross product of
// rows of (S - lam I). Output normalized.
// ---------------------------------------------------------------------------
__device__ __forceinline__ void eigvec_from_lambda(
    const float S[3][3], float lam, float v[3])
{
    float r0[3] = {S[0][0] - lam, S[0][1], S[0][2]};
    float r1[3] = {S[0][1], S[1][1] - lam, S[1][2]};
    float r2[3] = {S[0][2], S[1][2], S[2][2] - lam};

    float c01[3] = {r0[1] * r1[2] - r0[2] * r1[1],
                    r0[2] * r1[0] - r0[0] * r1[2],
                    r0[0] * r1[1] - r0[1] * r1[0]};
    float c02[3] = {r0[1] * r2[2] - r0[2] * r2[1],
                    r0[2] * r2[0] - r0[0] * r2[2],
                    r0[0] * r2[1] - r0[1] * r2[0]};
    float c12[3] = {r1[1] * r2[2] - r1[2] * r2[1],
                    r1[2] * r2[0] - r1[0] * r2[2],
                    r1[0] * r2[1] - r1[1] * r2[0]};

    float n01 = c01[0] * c01[0] + c01[1] * c01[1] + c01[2] * c01[2];
    float n02 = c02[0] * c02[0] + c02[1] * c02[1] + c02[2] * c02[2];
    float n12 = c12[0] * c12[0] + c12[1] * c12[1] + c12[2] * c12[2];

    float* best = c01;
    float  nb = n01;
    if (n02 > nb) { best = c02; nb = n02; }
    if (n12 > nb) { best = c12; nb = n12; }

    float inv = rsqrtf(nb + 1e-35f);
    v[0] = best[0] * inv;
    v[1] = best[1] * inv;
    v[2] = best[2] * inv;
}

// ---------------------------------------------------------------------------
// Kernel 2: per-batch solve. grid = B blocks, 32 threads (R6 layout).
// Closed-form eigensolver for S = H^T H.
// ---------------------------------------------------------------------------
__global__ __launch_bounds__(32) void svd_solve_kernel(float* __restrict__ out)
{
    const int b = blockIdx.x;
    __shared__ float sums[NV];

    if (threadIdx.x < NV) {
        float s = 0.0f;
#pragma unroll
        for (int c = 0; c < CHUNKS; c++)
            s += g_scratch[((size_t)b * CHUNKS + c) * NV + threadIdx.x];
        sums[threadIdx.x] = s;
    }
    __syncthreads();

    if (threadIdx.x != 0) return;

    const float invN = 1.0f / (float)N_DIM;
    float ms[3], mt[3], Sws[3], Swt[3], Sw, M[3][3];
#pragma unroll
    for (int i = 0; i < 3; i++) {
        ms[i]  = sums[i] * invN;
        mt[i]  = sums[3 + i] * invN;
        Sws[i] = sums[7 + i];
        Swt[i] = sums[10 + i];
    }
    Sw = sums[6];
#pragma unroll
    for (int i = 0; i < 3; i++)
#pragma unroll
        for (int j = 0; j < 3; j++)
            M[i][j] = sums[13 + i * 3 + j];

    // H_ij = sum w s_i t_j - ms_i*sum(w t_j) - mt_j*sum(w s_i) + ms_i mt_j sum(w)
    float H[3][3];
#pragma unroll
    for (int i = 0; i < 3; i++)
#pragma unroll
        for (int j = 0; j < 3; j++)
            H[i][j] = M[i][j] - ms[i] * Swt[j] - mt[j] * Sws[i] + ms[i] * mt[j] * Sw;

    // S = H^T H (symmetric PSD)
    float S[3][3];
#pragma unroll
    for (int i = 0; i < 3; i++)
#pragma unroll
        for (int j = 0; j < 3; j++) {
            float acc = 0.0f;
#pragma unroll
            for (int k = 0; k < 3; k++) acc += H[k][i] * H[k][j];
            S[i][j] = acc;
        }

    // Closed-form eigenvalues of 3x3 symmetric S (descending lam0 >= lam1).
    const float q  = (S[0][0] + S[1][1] + S[2][2]) * (1.0f / 3.0f);
    const float p1 = S[0][1] * S[0][1] + S[0][2] * S[0][2] + S[1][2] * S[1][2];
    const float d0 = S[0][0] - q, d1 = S[1][1] - q, d2 = S[2][2] - q;
    const float p2 = d0 * d0 + d1 * d1 + d2 * d2 + 2.0f * p1;
    const float p  = sqrtf(p2 * (1.0f / 6.0f) + 1e-35f);
    const float ip = __fdividef(1.0f, p);

    // det(B), B = (S - qI)/p
    const float b00 = d0 * ip, b11 = d1 * ip, b22 = d2 * ip;
    const float b01 = S[0][1] * ip, b02 = S[0][2] * ip, b12 = S[1][2] * ip;
    float detB = b00 * (b11 * b22 - b12 * b12)
               - b01 * (b01 * b22 - b12 * b02)
               + b02 * (b01 * b12 - b11 * b02);
    float r = 0.5f * detB;
    r = fminf(1.0f, fmaxf(-1.0f, r));

    const float phi = acosf(r) * (1.0f / 3.0f);
    const float twop = 2.0f * p;
    const float lam0 = q + twop * __cosf(phi);                         // largest
    const float lam2 = q + twop * __cosf(phi + 2.0943951023931953f);   // smallest
    const float lam1 = 3.0f * q - lam0 - lam2;                         // middle

    // Eigenvectors for lam0, lam1 via cross-product method.
    float v1[3], v2[3];
    eigvec_from_lambda(S, lam0, v1);
    eigvec_from_lambda(S, lam1, v2);

    // Orthogonalize v2 against v1 (cross-product vectors are approximate).
    {
        float d = v2[0] * v1[0] + v2[1] * v1[1] + v2[2] * v1[2];
#pragma unroll
        for (int i = 0; i < 3; i++) v2[i] -= d * v1[i];
        float inv = rsqrtf(v2[0] * v2[0] + v2[1] * v2[1] + v2[2] * v2[2] + 1e-35f);
#pragma unroll
        for (int i = 0; i < 3; i++) v2[i] *= inv;
    }

    // v3 = v1 x v2 -> det([v1 v2 v3]) = +1
    float v3[3] = {v1[1] * v2[2] - v1[2] * v2[1],
                   v1[2] * v2[0] - v1[0] * v2[2],
                   v1[0] * v2[1] - v1[1] * v2[0]};

    // u1 = normalize(H v1); u2 = normalize(GS(H v2, u1)); u3 = u1 x u2.
    float u1[3], u2[3], u3[3];
#pragma unroll
    for (int i = 0; i < 3; i++)
        u1[i] = H[i][0] * v1[0] + H[i][1] * v1[1] + H[i][2] * v1[2];
    float in1 = rsqrtf(u1[0] * u1[0] + u1[1] * u1[1] + u1[2] * u1[2] + 1e-35f);
#pragma unroll
    for (int i = 0; i < 3; i++) u1[i] *= in1;

#pragma unroll
    for (int i = 0; i < 3; i++)
        u2[i] = H[i][0] * v2[0] + H[i][1] * v2[1] + H[i][2] * v2[2];
    float d12 = u2[0] * u1[0] + u2[1] * u1[1] + u2[2] * u1[2];
#pragma unroll
    for (int i = 0; i < 3; i++) u2[i] -= d12 * u1[i];
    float in2 = rsqrtf(u2[0] * u2[0] + u2[1] * u2[1] + u2[2] * u2[2] + 1e-35f);
#pragma unroll
    for (int i = 0; i < 3; i++) u2[i] *= in2;

    u3[0] = u1[1] * u2[2] - u1[2] * u2[1];
    u3[1] = u1[2] * u2[0] - u1[0] * u2[2];
    u3[2] = u1[0] * u2[1] - u1[1] * u2[0];

    // R = v1 u1^T + v2 u2^T + v3 u3^T (proper rotation, det=+1).
    float R[3][3];
#pragma unroll
    for (int i = 0; i < 3; i++)
#pragma unroll
        for (int j = 0; j < 3; j++)
            R[i][j] = v1[i] * u1[j] + v2[i] * u2[j] + v3[i] * u3[j];

    // t = -R @ src_mean + tgt_mean ; t_out = -R^T t ; Rt = R^T
    float tv[3];
#pragma unroll
    for (int i = 0; i < 3; i++)
        tv[i] = -(R[i][0] * ms[0] + R[i][1] * ms[1] + R[i][2] * ms[2]) + mt[i];

    float* outR = out + (size_t)b * 9;
    float* outT = out + (size_t)B_DIM * 9 + (size_t)b * 3;
#pragma unroll
    for (int i = 0; i < 3; i++) {
#pragma unroll
        for (int j = 0; j < 3; j++)
            outR[i * 3 + j] = R[j][i];  // Rt = R^T
        outT[i] = -(R[0][i] * tv[0] + R[1][i] * tv[1] + R[2][i] * tv[2]);
    }
}

extern "C" void kernel_launch(void* const* d_in, const int* in_sizes, int n_in,
                              void* d_out, int out_size)
{
    const float* src = (const float*)d_in[0];
    const float* tgt = (const float*)d_in[1];
    const float* wgt = (const float*)d_in[2];
    float* out = (float*)d_out;

    svd_reduce_kernel<<<B_DIM * CHUNKS, TPB>>>(src, tgt, wgt);
    svd_solve_kernel<<<B_DIM, 32>>>(out);
}